// round 16
// baseline (speedup 1.0000x reference)
#include <cuda_runtime.h>
#include <cstdint>

#define DEV_INLINE __device__ __forceinline__

static constexpr int M = 2048, K = 4096, N = 11008;
static constexpr int BM = 128, BN = 256, BK = 128;
static constexpr int STAGES = 4;
static constexpr int PANEL = 16384;                 // 128 rows x 128B, swizzled
static constexpr int STAGE_BYTES = 3 * PANEL;       // A + B0 + B1 = 49152
static constexpr int SMEM_CTRL = 1024;
static constexpr int SMEM_TOTAL = SMEM_CTRL + STAGES * STAGE_BYTES;  // 197632
static constexpr int MAX_BLOCKS = 1024;
static constexpr int TILES_M = M / BM;              // 16
static constexpr int TILES_NP = N / 128;            // 86 (storage panels, 128 rows)
static constexpr int TILES_N2 = N / BN;             // 43
static constexpr int NTILES = TILES_M * TILES_N2;   // 688
static constexpr int KT = K / 128;                  // 32
static constexpr int GEMM_CTAS = 148;               // 1 per SM, persistent

__device__ __align__(128) int8_t g_xqT[(size_t)TILES_M * KT * PANEL];
__device__ __align__(128) int8_t g_wtT[(size_t)TILES_NP * KT * PANEL];
__device__ float g_partial[MAX_BLOCKS];
__device__ float g_scale;
__device__ unsigned g_tile_ctr;

// ============================ PTX helpers ============================

DEV_INLINE uint32_t smem_u32(const void* p) {
  uint32_t a;
  asm("{ .reg .u64 t; cvta.to.shared.u64 t, %1; cvt.u32.u64 %0, t; }"
      : "=r"(a) : "l"(p));
  return a;
}

#define MBARRIER_INIT(addr, cnt) \
  asm volatile("mbarrier.init.shared.b64 [%0], %1;" \
               :: "r"((uint32_t)(addr)), "r"((uint32_t)(cnt)) : "memory")

#define MBARRIER_EXPECT_TX(addr, bytes) \
  asm volatile("mbarrier.arrive.expect_tx.shared.b64 _, [%0], %1;" \
               :: "r"((uint32_t)(addr)), "r"((uint32_t)(bytes)) : "memory")

#define MBARRIER_WAIT_PARITY(mbar_smem_addr, phase_parity) do {              \
  uint32_t _mbar = (uint32_t)(mbar_smem_addr);                               \
  uint32_t _parity = (uint32_t)(phase_parity);                               \
  uint32_t _done;                                                            \
  asm volatile(                                                              \
      "{\n\t"                                                                \
      ".reg .pred p;\n\t"                                                    \
      "mbarrier.try_wait.parity.acquire.cta.shared::cta.b64 p, [%1], %2;\n\t"\
      "selp.b32 %0, 1, 0, p;\n\t"                                            \
      "}"                                                                    \
      : "=r"(_done) : "r"(_mbar), "r"(_parity) : "memory");                  \
  if (!_done) {                                                              \
    asm volatile(                                                            \
        "{\n\t"                                                              \
        ".reg .pred P1;\n\t"                                                 \
        "WAIT_LOOP_%=:\n\t"                                                  \
        "mbarrier.try_wait.parity.acquire.cta.shared::cta.b64 P1, [%0], %1, 0x989680;\n\t" \
        "@P1 bra.uni WAIT_DONE_%=;\n\t"                                      \
        "bra.uni WAIT_LOOP_%=;\n\t"                                          \
        "WAIT_DONE_%=:\n\t"                                                  \
        "}"                                                                  \
        :: "r"(_mbar), "r"(_parity) : "memory");                             \
  }                                                                          \
} while (0)

DEV_INLINE void bulk_g2s(uint32_t dst, const void* src, uint32_t mbar) {
  asm volatile(
      "cp.async.bulk.shared::cta.global.mbarrier::complete_tx::bytes "
      "[%0], [%1], %2, [%3];"
      :: "r"(dst), "l"(src), "r"((uint32_t)PANEL), "r"(mbar) : "memory");
}

// Non-volatile: ptxas schedules freely (proven on this toolchain R11-R15).
DEV_INLINE void ldsm_x4(uint32_t& r0, uint32_t& r1, uint32_t& r2, uint32_t& r3,
                        uint32_t addr) {
  asm("ldmatrix.sync.aligned.m8n8.x4.shared.b16 {%0,%1,%2,%3}, [%4];"
      : "=r"(r0), "=r"(r1), "=r"(r2), "=r"(r3) : "r"(addr));
}

DEV_INLINE void mma_s8(int& c0, int& c1, int& c2, int& c3,
                       uint32_t a0, uint32_t a1, uint32_t a2, uint32_t a3,
                       uint32_t b0, uint32_t b1) {
  asm("mma.sync.aligned.m16n8k32.row.col.s32.s8.s8.s32 "
      "{%0,%1,%2,%3}, {%4,%5,%6,%7}, {%8,%9}, {%0,%1,%2,%3};"
      : "+r"(c0), "+r"(c1), "+r"(c2), "+r"(c3)
      : "r"(a0), "r"(a1), "r"(a2), "r"(a3), "r"(b0), "r"(b1));
}

// ============================ pre-pass kernels ============================

__global__ void __launch_bounds__(256) k_maxabs(const float4* __restrict__ x) {
  if (blockIdx.x == 0 && threadIdx.x == 0) g_tile_ctr = 0u;
  const int n4 = M * K / 4;
  float m = 0.0f;
  for (int i = blockIdx.x * blockDim.x + threadIdx.x; i < n4;
       i += gridDim.x * blockDim.x) {
    float4 v = x[i];
    m = fmaxf(m, fmaxf(fmaxf(fabsf(v.x), fabsf(v.y)),
                       fmaxf(fabsf(v.z), fabsf(v.w))));
  }
  #pragma unroll
  for (int o = 16; o > 0; o >>= 1) m = fmaxf(m, __shfl_xor_sync(0xFFFFFFFFu, m, o));
  __shared__ float red[8];
  if ((threadIdx.x & 31) == 0) red[threadIdx.x >> 5] = m;
  __syncthreads();
  if (threadIdx.x == 0) {
    float t = red[0];
    #pragma unroll
    for (int j = 1; j < 8; ++j) t = fmaxf(t, red[j]);
    g_partial[blockIdx.x] = t;
  }
}

__global__ void __launch_bounds__(256) k_quant(const float4* __restrict__ x) {
  __shared__ float red[8];
  __shared__ float bcast;
  {
    float m = 0.0f;
    #pragma unroll
    for (int j = 0; j < MAX_BLOCKS / 256; ++j)
      m = fmaxf(m, g_partial[threadIdx.x + j * 256]);
    #pragma unroll
    for (int o = 16; o > 0; o >>= 1)
      m = fmaxf(m, __shfl_xor_sync(0xFFFFFFFFu, m, o));
    if ((threadIdx.x & 31) == 0) red[threadIdx.x >> 5] = m;
    __syncthreads();
    if (threadIdx.x == 0) {
      float t = red[0];
      #pragma unroll
      for (int j = 1; j < 8; ++j) t = fmaxf(t, red[j]);
      bcast = t;
      if (blockIdx.x == 0) g_scale = t * (1.0f / 128.0f);
    }
    __syncthreads();
  }
  const float scale = bcast * (1.0f / 128.0f);

  const int idx = blockIdx.x * 256 + threadIdx.x;   // one 16-elem chunk
  const int m = idx >> 8;
  const int cq = idx & 255;
  const float4* xs = x + (size_t)m * (K / 4) + cq * 4;
  uint32_t w[4];
  #pragma unroll
  for (int j = 0; j < 4; ++j) {
    float4 v = xs[j];
    int a = __float2int_rn(__fdiv_rn(v.x, scale));
    int b = __float2int_rn(__fdiv_rn(v.y, scale));
    int c = __float2int_rn(__fdiv_rn(v.z, scale));
    int d = __float2int_rn(__fdiv_rn(v.w, scale));
    a = max(-128, min(127, a)); b = max(-128, min(127, b));
    c = max(-128, min(127, c)); d = max(-128, min(127, d));
    w[j] = (uint32_t)(uint8_t)(int8_t)a
         | ((uint32_t)(uint8_t)(int8_t)b << 8)
         | ((uint32_t)(uint8_t)(int8_t)c << 16)
         | ((uint32_t)(uint8_t)(int8_t)d << 24);
  }
  const int tile_m = m >> 7, r = m & 127;
  const int kt = cq >> 3, c = cq & 7;
  uint4* dst = (uint4*)(g_xqT + ((size_t)(tile_m * KT + kt)) * PANEL
                        + r * 128 + ((c ^ (r & 7)) << 4));
  *dst = make_uint4(w[0], w[1], w[2], w[3]);
}

__global__ void __launch_bounds__(256) k_transpose(const int4* __restrict__ W32) {
  __shared__ int8_t tile[64][68];
  const int k0 = blockIdx.x * 64;
  const int n0 = blockIdx.y * 64;
  const int t = threadIdx.x;
  const int Nv = N / 4;

  #pragma unroll
  for (int it = 0; it < 4; ++it) {
    int idx = t + it * 256;
    int r = idx >> 4;
    int cv = idx & 15;
    int4 v = W32[(size_t)(k0 + r) * Nv + (n0 >> 2) + cv];
    uint32_t w = (uint32_t)(uint8_t)(int8_t)v.x
               | ((uint32_t)(uint8_t)(int8_t)v.y << 8)
               | ((uint32_t)(uint8_t)(int8_t)v.z << 16)
               | ((uint32_t)(uint8_t)(int8_t)v.w << 24);
    *(uint32_t*)&tile[r][cv * 4] = w;
  }
  __syncthreads();

  const int n = t >> 2;
  const int kc = t & 3;
  uint32_t w[4];
  #pragma unroll
  for (int j4 = 0; j4 < 4; ++j4) {
    w[j4] = (uint32_t)(uint8_t)tile[kc * 16 + j4 * 4 + 0][n]
          | ((uint32_t)(uint8_t)tile[kc * 16 + j4 * 4 + 1][n] << 8)
          | ((uint32_t)(uint8_t)tile[kc * 16 + j4 * 4 + 2][n] << 16)
          | ((uint32_t)(uint8_t)tile[kc * 16 + j4 * 4 + 3][n] << 24);
  }
  const int gn = n0 + n;
  const int gk = k0 + kc * 16;
  const int tile_n = gn >> 7, r = gn & 127;
  const int kt = gk >> 7, c = (gk >> 4) & 7;
  uint4* dst = (uint4*)(g_wtT + ((size_t)(tile_n * KT + kt)) * PANEL
                        + r * 128 + ((c ^ (r & 7)) << 4));
  *dst = make_uint4(w[0], w[1], w[2], w[3]);
}

// ============================ GEMM kernel ============================
// Persistent, 148 CTAs (1/SM), 8 warps, warp tile 64x64, CTA 128x256x128.
// One continuous 4-slot mbarrier ring across ALL tiles: producer (tid 0)
// streams (tile, k)-panels, fetching tile ids 3 steps ahead; epilogues and
// tile prologues overlap the stream.

DEV_INLINE void issue_stage(uint32_t sbase, int slot, int tile, int kt) {
  const int tm = tile % TILES_M;
  const int tn2 = tile / TILES_M;
  const uint32_t mb = sbase + slot * 8;
  const uint32_t st = sbase + SMEM_CTRL + slot * STAGE_BYTES;
  MBARRIER_EXPECT_TX(mb, STAGE_BYTES);
  bulk_g2s(st, g_xqT + ((size_t)(tm * KT + kt)) * PANEL, mb);
  bulk_g2s(st + PANEL,
           g_wtT + ((size_t)((2 * tn2) * KT + kt)) * PANEL, mb);
  bulk_g2s(st + 2 * PANEL,
           g_wtT + ((size_t)((2 * tn2 + 1) * KT + kt)) * PANEL, mb);
}

__global__ void __launch_bounds__(256, 1)
qlinear_gemm(const float* __restrict__ bias, float* __restrict__ out) {
  extern __shared__ __align__(16) char smem[];
  const uint32_t sbase = smem_u32(smem);
  const int tid = threadIdx.x;
  const int wid = tid >> 5;
  const int lane = tid & 31;
  const int wm = wid & 1;        // 2 warps along m (64 rows each)
  const int wn = wid >> 1;       // 4 warps along n (64 cols each)

  const int row_in = lane & 7;
  const int b = lane >> 3;
  const int a_row = wm * 64 + (b & 1) * 8 + row_in;      // + mt*16
  const int a_csel = b >> 1;
  const int b_half_off = (wn >> 1) * PANEL;              // which B half-panel
  const int b_rowl = (wn & 1) * 64 + (b >> 1) * 8 + row_in;  // + p*16
  const int b_csel = b & 1;

  const float s = g_scale * 0.0123f;
  const int gr = lane >> 2;
  const int gc = (lane & 3) << 1;

  __shared__ int s_tid[2];   // tile ids, indexed by (step/32)&1

  // ---- init: barriers + first tile + prologue (3 stages) ----
  int ld_tile = 0;           // producer-private (valid in tid 0 only)
  if (tid == 0) {
    #pragma unroll
    for (int ss = 0; ss < STAGES; ++ss) MBARRIER_INIT(sbase + ss * 8, 1);
    ld_tile = (int)atomicAdd(&g_tile_ctr, 1u);
    s_tid[0] = ld_tile;
    if (ld_tile < NTILES) {
      #pragma unroll
      for (int j = 0; j < STAGES - 1; ++j)
        issue_stage(sbase, j, ld_tile, j);
    }
  }
  __syncthreads();

  int c[4][8][4];
  int cur_tile = 0, m0 = 0, n0 = 0;

  for (int cg = 0;; ++cg) {
    const int kt = cg & 31;
    if (kt == 0) {
      cur_tile = s_tid[(cg >> 5) & 1];
      if (cur_tile >= NTILES) break;
      m0 = (cur_tile % TILES_M) * BM;
      n0 = (cur_tile / TILES_M) * BN;
      #pragma unroll
      for (int i = 0; i < 4; ++i)
        #pragma unroll
        for (int j = 0; j < 8; ++j)
          #pragma unroll
          for (int q = 0; q < 4; ++q) c[i][j][q] = 0;
    }

    const int slot = cg & 3;
    MBARRIER_WAIT_PARITY(sbase + slot * 8, (uint32_t)((cg >> 2) & 1));
    const uint32_t stA = sbase + SMEM_CTRL + slot * STAGE_BYTES;
    const uint32_t stB = stA + PANEL + b_half_off;

    #pragma unroll
    for (int ss = 0; ss < 4; ++ss) {           // four k32 steps
      uint32_t a[4][4], bb[8][2];
      const int ca = (2 * ss + a_csel) ^ row_in;
      const int cb = (2 * ss + b_csel) ^ row_in;
      #pragma unroll
      for (int mt = 0; mt < 4; ++mt)
        ldsm_x4(a[mt][0], a[mt][1], a[mt][2], a[mt][3],
                stA + (a_row + mt * 16) * 128 + (ca << 4));
      #pragma unroll
      for (int p = 0; p < 4; ++p) {
        uint32_t r0, r1, r2, r3;
        ldsm_x4(r0, r1, r2, r3,
                stB + (b_rowl + p * 16) * 128 + (cb << 4));
        bb[2 * p][0] = r0; bb[2 * p][1] = r1;
        bb[2 * p + 1][0] = r2; bb[2 * p + 1][1] = r3;
      }
      #pragma unroll
      for (int mt = 0; mt < 4; ++mt)
        #pragma unroll
        for (int nt = 0; nt < 8; ++nt)
          mma_s8(c[mt][nt][0], c[mt][nt][1], c[mt][nt][2], c[mt][nt][3],
                 a[mt][0], a[mt][1], a[mt][2], a[mt][3],
                 bb[nt][0], bb[nt][1]);
    }

    __syncthreads();   // slot consumed CTA-wide; producer may recycle
    if (tid == 0) {
      const int lg = cg + STAGES - 1;
      const int lkt = lg & 31;
      if (lkt == 0) {  // crossing into next tile: fetch its id
        ld_tile = (int)atomicAdd(&g_tile_ctr, 1u);
        s_tid[(lg >> 5) & 1] = ld_tile;
      }
      if (ld_tile < NTILES)
        issue_stage(sbase, lg & 3, ld_tile, lkt);
    }

    if (kt == 31) {
      // epilogue (overlaps next tile's in-flight prologue loads)
      #pragma unroll
      for (int mt = 0; mt < 4; ++mt) {
        const int m = m0 + wm * 64 + mt * 16 + gr;
        float* __restrict__ row0 = out + (size_t)m * N;
        float* __restrict__ row1 = row0 + (size_t)8 * N;
        #pragma unroll
        for (int nt = 0; nt < 8; ++nt) {
          const int col = n0 + wn * 64 + nt * 8 + gc;
          const float2 bv = *(const float2*)(bias + col);
          float2 v0, v1;
          v0.x = fmaf((float)c[mt][nt][0], s, bv.x);
          v0.y = fmaf((float)c[mt][nt][1], s, bv.y);
          v1.x = fmaf((float)c[mt][nt][2], s, bv.x);
          v1.y = fmaf((float)c[mt][nt][3], s, bv.y);
          *(float2*)(row0 + col) = v0;
          *(float2*)(row1 + col) = v1;
        }
      }
    }
  }
}

// ============================ launch ============================

extern "C" void kernel_launch(void* const* d_in, const int* in_sizes, int n_in,
                              void* d_out, int out_size) {
  const float* x    = (const float*)d_in[0];
  const int*   W32  = (const int*)d_in[1];    // int8 weights promoted to int32
  const float* bias = (const float*)d_in[2];
  float* out = (float*)d_out;

  k_maxabs<<<MAX_BLOCKS, 256>>>((const float4*)x);
  k_quant<<<M * K / 16 / 256, 256>>>((const float4*)x);
  {
    dim3 tg(K / 64, N / 64);    // 64 x 172
    k_transpose<<<tg, 256>>>((const int4*)W32);
  }

  cudaFuncSetAttribute(qlinear_gemm,
                       cudaFuncAttributeMaxDynamicSharedMemorySize, SMEM_TOTAL);
  qlinear_gemm<<<GEMM_CTAS, 256, SMEM_TOTAL>>>(bias, out);
}

// round 17
// speedup vs baseline: 1.0848x; 1.0848x over previous
#include <cuda_runtime.h>
#include <cstdint>

#define DEV_INLINE __device__ __forceinline__

static constexpr int M = 2048, K = 4096, N = 11008;
static constexpr int BM = 128, BN = 128, BK = 128;
static constexpr int STAGES = 3;
static constexpr int PANEL = 16384;                 // 128 rows x 128B, swizzled
static constexpr int STAGE_BYTES = 2 * PANEL;       // 32768
static constexpr int SMEM_CTRL = 1024;
static constexpr int SMEM_TOTAL = SMEM_CTRL + STAGES * STAGE_BYTES;  // 99328 -> 2/SM
static constexpr int MAX_BLOCKS = 1024;
static constexpr int TILES_M = M / BM;              // 16
static constexpr int TILES_N = N / BN;              // 86
static constexpr int NTILES = TILES_M * TILES_N;    // 1376
static constexpr int KT = K / 128;                  // 32
static constexpr int GEMM_CTAS = 296;               // 2 per SM, persistent

__device__ __align__(128) int8_t g_xqT[(size_t)TILES_M * KT * PANEL];
__device__ __align__(128) int8_t g_wtT[(size_t)TILES_N * KT * PANEL];
__device__ float g_partial[MAX_BLOCKS];
__device__ float g_scale;
__device__ unsigned g_tile_ctr;

// ============================ PTX helpers ============================

DEV_INLINE uint32_t smem_u32(const void* p) {
  uint32_t a;
  asm("{ .reg .u64 t; cvta.to.shared.u64 t, %1; cvt.u32.u64 %0, t; }"
      : "=r"(a) : "l"(p));
  return a;
}

#define MBARRIER_INIT(addr, cnt) \
  asm volatile("mbarrier.init.shared.b64 [%0], %1;" \
               :: "r"((uint32_t)(addr)), "r"((uint32_t)(cnt)) : "memory")

#define MBARRIER_EXPECT_TX(addr, bytes) \
  asm volatile("mbarrier.arrive.expect_tx.shared.b64 _, [%0], %1;" \
               :: "r"((uint32_t)(addr)), "r"((uint32_t)(bytes)) : "memory")

#define MBARRIER_ARRIVE(addr) \
  asm volatile("mbarrier.arrive.shared.b64 _, [%0];" \
               :: "r"((uint32_t)(addr)) : "memory")

#define FENCE_ASYNC_SHARED() \
  asm volatile("fence.proxy.async.shared::cta;" ::: "memory")

#define MBARRIER_WAIT_PARITY(mbar_smem_addr, phase_parity) do {              \
  uint32_t _mbar = (uint32_t)(mbar_smem_addr);                               \
  uint32_t _parity = (uint32_t)(phase_parity);                               \
  uint32_t _done;                                                            \
  asm volatile(                                                              \
      "{\n\t"                                                                \
      ".reg .pred p;\n\t"                                                    \
      "mbarrier.try_wait.parity.acquire.cta.shared::cta.b64 p, [%1], %2;\n\t"\
      "selp.b32 %0, 1, 0, p;\n\t"                                            \
      "}"                                                                    \
      : "=r"(_done) : "r"(_mbar), "r"(_parity) : "memory");                  \
  if (!_done) {                                                              \
    asm volatile(                                                            \
        "{\n\t"                                                              \
        ".reg .pred P1;\n\t"                                                 \
        "WAIT_LOOP_%=:\n\t"                                                  \
        "mbarrier.try_wait.parity.acquire.cta.shared::cta.b64 P1, [%0], %1, 0x989680;\n\t" \
        "@P1 bra.uni WAIT_DONE_%=;\n\t"                                      \
        "bra.uni WAIT_LOOP_%=;\n\t"                                          \
        "WAIT_DONE_%=:\n\t"                                                  \
        "}"                                                                  \
        :: "r"(_mbar), "r"(_parity) : "memory");                             \
  }                                                                          \
} while (0)

DEV_INLINE void bulk_g2s(uint32_t dst, const void* src, uint32_t mbar) {
  asm volatile(
      "cp.async.bulk.shared::cta.global.mbarrier::complete_tx::bytes "
      "[%0], [%1], %2, [%3];"
      :: "r"(dst), "l"(src), "r"((uint32_t)PANEL), "r"(mbar) : "memory");
}

// Non-volatile: ptxas schedules freely (proven on this toolchain R11-R15).
DEV_INLINE void ldsm_x4(uint32_t& r0, uint32_t& r1, uint32_t& r2, uint32_t& r3,
                        uint32_t addr) {
  asm("ldmatrix.sync.aligned.m8n8.x4.shared.b16 {%0,%1,%2,%3}, [%4];"
      : "=r"(r0), "=r"(r1), "=r"(r2), "=r"(r3) : "r"(addr));
}

DEV_INLINE void mma_s8(int& c0, int& c1, int& c2, int& c3,
                       uint32_t a0, uint32_t a1, uint32_t a2, uint32_t a3,
                       uint32_t b0, uint32_t b1) {
  asm("mma.sync.aligned.m16n8k32.row.col.s32.s8.s8.s32 "
      "{%0,%1,%2,%3}, {%4,%5,%6,%7}, {%8,%9}, {%0,%1,%2,%3};"
      : "+r"(c0), "+r"(c1), "+r"(c2), "+r"(c3)
      : "r"(a0), "r"(a1), "r"(a2), "r"(a3), "r"(b0), "r"(b1));
}

// ============================ pre-pass kernels ============================

__global__ void __launch_bounds__(256) k_maxabs(const float4* __restrict__ x) {
  if (blockIdx.x == 0 && threadIdx.x == 0) g_tile_ctr = 0u;
  const int n4 = M * K / 4;
  float m = 0.0f;
  for (int i = blockIdx.x * blockDim.x + threadIdx.x; i < n4;
       i += gridDim.x * blockDim.x) {
    float4 v = x[i];
    m = fmaxf(m, fmaxf(fmaxf(fabsf(v.x), fabsf(v.y)),
                       fmaxf(fabsf(v.z), fabsf(v.w))));
  }
  #pragma unroll
  for (int o = 16; o > 0; o >>= 1) m = fmaxf(m, __shfl_xor_sync(0xFFFFFFFFu, m, o));
  __shared__ float red[8];
  if ((threadIdx.x & 31) == 0) red[threadIdx.x >> 5] = m;
  __syncthreads();
  if (threadIdx.x == 0) {
    float t = red[0];
    #pragma unroll
    for (int j = 1; j < 8; ++j) t = fmaxf(t, red[j]);
    g_partial[blockIdx.x] = t;
  }
}

__global__ void __launch_bounds__(256) k_quant(const float4* __restrict__ x) {
  __shared__ float red[8];
  __shared__ float bcast;
  {
    float m = 0.0f;
    #pragma unroll
    for (int j = 0; j < MAX_BLOCKS / 256; ++j)
      m = fmaxf(m, g_partial[threadIdx.x + j * 256]);
    #pragma unroll
    for (int o = 16; o > 0; o >>= 1)
      m = fmaxf(m, __shfl_xor_sync(0xFFFFFFFFu, m, o));
    if ((threadIdx.x & 31) == 0) red[threadIdx.x >> 5] = m;
    __syncthreads();
    if (threadIdx.x == 0) {
      float t = red[0];
      #pragma unroll
      for (int j = 1; j < 8; ++j) t = fmaxf(t, red[j]);
      bcast = t;
      if (blockIdx.x == 0) g_scale = t * (1.0f / 128.0f);
    }
    __syncthreads();
  }
  const float scale = bcast * (1.0f / 128.0f);

  const int idx = blockIdx.x * 256 + threadIdx.x;   // one 16-elem chunk
  const int m = idx >> 8;
  const int cq = idx & 255;
  const float4* xs = x + (size_t)m * (K / 4) + cq * 4;
  uint32_t w[4];
  #pragma unroll
  for (int j = 0; j < 4; ++j) {
    float4 v = xs[j];
    int a = __float2int_rn(__fdiv_rn(v.x, scale));
    int b = __float2int_rn(__fdiv_rn(v.y, scale));
    int c = __float2int_rn(__fdiv_rn(v.z, scale));
    int d = __float2int_rn(__fdiv_rn(v.w, scale));
    a = max(-128, min(127, a)); b = max(-128, min(127, b));
    c = max(-128, min(127, c)); d = max(-128, min(127, d));
    w[j] = (uint32_t)(uint8_t)(int8_t)a
         | ((uint32_t)(uint8_t)(int8_t)b << 8)
         | ((uint32_t)(uint8_t)(int8_t)c << 16)
         | ((uint32_t)(uint8_t)(int8_t)d << 24);
  }
  const int tile_m = m >> 7, r = m & 127;
  const int kt = cq >> 3, c = cq & 7;
  uint4* dst = (uint4*)(g_xqT + ((size_t)(tile_m * KT + kt)) * PANEL
                        + r * 128 + ((c ^ (r & 7)) << 4));
  *dst = make_uint4(w[0], w[1], w[2], w[3]);
}

__global__ void __launch_bounds__(256) k_transpose(const int4* __restrict__ W32) {
  __shared__ int8_t tile[64][68];
  const int k0 = blockIdx.x * 64;
  const int n0 = blockIdx.y * 64;
  const int t = threadIdx.x;
  const int Nv = N / 4;

  #pragma unroll
  for (int it = 0; it < 4; ++it) {
    int idx = t + it * 256;
    int r = idx >> 4;
    int cv = idx & 15;
    int4 v = W32[(size_t)(k0 + r) * Nv + (n0 >> 2) + cv];
    uint32_t w = (uint32_t)(uint8_t)(int8_t)v.x
               | ((uint32_t)(uint8_t)(int8_t)v.y << 8)
               | ((uint32_t)(uint8_t)(int8_t)v.z << 16)
               | ((uint32_t)(uint8_t)(int8_t)v.w << 24);
    *(uint32_t*)&tile[r][cv * 4] = w;
  }
  __syncthreads();

  const int n = t >> 2;
  const int kc = t & 3;
  uint32_t w[4];
  #pragma unroll
  for (int j4 = 0; j4 < 4; ++j4) {
    w[j4] = (uint32_t)(uint8_t)tile[kc * 16 + j4 * 4 + 0][n]
          | ((uint32_t)(uint8_t)tile[kc * 16 + j4 * 4 + 1][n] << 8)
          | ((uint32_t)(uint8_t)tile[kc * 16 + j4 * 4 + 2][n] << 16)
          | ((uint32_t)(uint8_t)tile[kc * 16 + j4 * 4 + 3][n] << 24);
  }
  const int gn = n0 + n;
  const int gk = k0 + kc * 16;
  const int tile_n = gn >> 7, r = gn & 127;
  const int kt = gk >> 7, c = (gk >> 4) & 7;
  uint4* dst = (uint4*)(g_wtT + ((size_t)(tile_n * KT + kt)) * PANEL
                        + r * 128 + ((c ^ (r & 7)) << 4));
  *dst = make_uint4(w[0], w[1], w[2], w[3]);
}

// ============================ GEMM kernel ============================
// Persistent, 296 CTAs (2/SM), 8 warps, warp tile 64x32, CTA 128x128x128.
// Continuous 3-slot ring across ALL tiles with full/empty mbarrier pairs:
// no per-iteration __syncthreads (warps may skew up to 2 stages), no
// per-tile barrier re-init or pipeline drain. Producer = tid 0.
// SMEM ctrl layout: full[3] @ +0, empty[3] @ +24, s_tid[2] @ +48.

DEV_INLINE void issue_stage(uint32_t sbase, int slot, int tile, int kt) {
  const int tm = tile % TILES_M;
  const int tn = tile / TILES_M;
  const uint32_t mb = sbase + slot * 8;
  const uint32_t st = sbase + SMEM_CTRL + slot * STAGE_BYTES;
  MBARRIER_EXPECT_TX(mb, STAGE_BYTES);
  bulk_g2s(st, g_xqT + ((size_t)(tm * KT + kt)) * PANEL, mb);
  bulk_g2s(st + PANEL, g_wtT + ((size_t)(tn * KT + kt)) * PANEL, mb);
}

__global__ void __launch_bounds__(256, 2)
qlinear_gemm(const float* __restrict__ bias, float* __restrict__ out) {
  extern __shared__ __align__(16) char smem[];
  const uint32_t sbase = smem_u32(smem);
  int* s_tid = (int*)(smem + 48);
  const int tid = threadIdx.x;
  const int wid = tid >> 5;
  const int lane = tid & 31;
  const int wm = wid & 1;        // 2 warps along m
  const int wn = wid >> 1;       // 4 warps along n

  // ldmatrix lane roles (proven R7/R8)
  const int row_in = lane & 7;
  const int b = lane >> 3;
  const int a_row = wm * 64 + (b & 1) * 8 + row_in;   // + mt*16
  const int a_csel = b >> 1;
  const int b_row = wn * 32 + (b >> 1) * 8 + row_in;  // + p*16
  const int b_csel = b & 1;

  const float s = g_scale * 0.0123f;
  const int gr = lane >> 2;
  const int gc = (lane & 3) << 1;

  // ---- one-time init: barriers + first tile + 2-stage prologue ----
  int ld_tile = 0;               // producer-private (tid 0)
  if (tid == 0) {
    #pragma unroll
    for (int ss = 0; ss < STAGES; ++ss) {
      MBARRIER_INIT(sbase + ss * 8, 1);        // full: producer expect_tx
      MBARRIER_INIT(sbase + 24 + ss * 8, 256); // empty: all threads arrive
    }
    FENCE_ASYNC_SHARED();
    ld_tile = (int)atomicAdd(&g_tile_ctr, 1u);
    s_tid[0] = ld_tile;
    const int t0 = (ld_tile < NTILES) ? ld_tile : 0;
    issue_stage(sbase, 0, t0, 0);
    issue_stage(sbase, 1, t0, 1);
  }
  __syncthreads();

  int c[4][4][4];
  int cur_tile = 0, m0 = 0, n0 = 0;

  for (int cg = 0;; ++cg) {
    const int kt = cg & 31;
    const int slot = cg % 3;
    const int inst = cg / 3;
    MBARRIER_WAIT_PARITY(sbase + slot * 8, (uint32_t)(inst & 1));

    if (kt == 0) {
      cur_tile = s_tid[(cg >> 5) & 1];   // ordered by full-barrier acquire
      if (cur_tile >= NTILES) break;
      m0 = (cur_tile % TILES_M) * BM;
      n0 = (cur_tile / TILES_M) * BN;
      #pragma unroll
      for (int i = 0; i < 4; ++i)
        #pragma unroll
        for (int j = 0; j < 4; ++j)
          #pragma unroll
          for (int q = 0; q < 4; ++q) c[i][j][q] = 0;
    }

    const uint32_t stA = sbase + SMEM_CTRL + slot * STAGE_BYTES;
    const uint32_t stB = stA + PANEL;

    #pragma unroll
    for (int ss = 0; ss < 4; ++ss) {           // four k32 steps
      uint32_t a[4][4], bb[4][2];
      const int ca = (2 * ss + a_csel) ^ row_in;
      const int cb = (2 * ss + b_csel) ^ row_in;
      #pragma unroll
      for (int mt = 0; mt < 4; ++mt)
        ldsm_x4(a[mt][0], a[mt][1], a[mt][2], a[mt][3],
                stA + (a_row + mt * 16) * 128 + (ca << 4));
      #pragma unroll
      for (int p = 0; p < 2; ++p) {
        uint32_t r0, r1, r2, r3;
        ldsm_x4(r0, r1, r2, r3,
                stB + (b_row + p * 16) * 128 + (cb << 4));
        bb[2 * p][0] = r0; bb[2 * p][1] = r1;
        bb[2 * p + 1][0] = r2; bb[2 * p + 1][1] = r3;
      }
      #pragma unroll
      for (int mt = 0; mt < 4; ++mt)
        #pragma unroll
        for (int nt = 0; nt < 4; ++nt)
          mma_s8(c[mt][nt][0], c[mt][nt][1], c[mt][nt][2], c[mt][nt][3],
                 a[mt][0], a[mt][1], a[mt][2], a[mt][3],
                 bb[nt][0], bb[nt][1]);
    }

    MBARRIER_ARRIVE(sbase + 24 + slot * 8);    // this thread done with slot

    if (tid == 0) {
      const int lg = cg + STAGES - 1;          // stage to issue now
      const int lslot = lg % 3;
      const int lm = lg / 3;
      if (lg >= STAGES)                        // recycle: prior data consumed?
        MBARRIER_WAIT_PARITY(sbase + 24 + lslot * 8, (uint32_t)((lm - 1) & 1));
      const int lkt = lg & 31;
      if (lkt == 0) {                          // crossing into next tile
        ld_tile = (int)atomicAdd(&g_tile_ctr, 1u);
        s_tid[(lg >> 5) & 1] = ld_tile;        // ordered by expect_tx release
      }
      issue_stage(sbase, lslot, (ld_tile < NTILES) ? ld_tile : 0, lkt);
    }

    if (kt == 31) {
      // epilogue overlaps next tile's in-flight loads
      #pragma unroll
      for (int mt = 0; mt < 4; ++mt) {
        const int m = m0 + wm * 64 + mt * 16 + gr;
        float* __restrict__ row0 = out + (size_t)m * N;
        float* __restrict__ row1 = row0 + (size_t)8 * N;
        #pragma unroll
        for (int nt = 0; nt < 4; ++nt) {
          const int col = n0 + wn * 32 + nt * 8 + gc;
          const float2 bv = *(const float2*)(bias + col);
          float2 v0, v1;
          v0.x = fmaf((float)c[mt][nt][0], s, bv.x);
          v0.y = fmaf((float)c[mt][nt][1], s, bv.y);
          v1.x = fmaf((float)c[mt][nt][2], s, bv.x);
          v1.y = fmaf((float)c[mt][nt][3], s, bv.y);
          *(float2*)(row0 + col) = v0;
          *(float2*)(row1 + col) = v1;
        }
      }
    }
  }
}

// ============================ launch ============================

extern "C" void kernel_launch(void* const* d_in, const int* in_sizes, int n_in,
                              void* d_out, int out_size) {
  const float* x    = (const float*)d_in[0];
  const int*   W32  = (const int*)d_in[1];    // int8 weights promoted to int32
  const float* bias = (const float*)d_in[2];
  float* out = (float*)d_out;

  k_maxabs<<<MAX_BLOCKS, 256>>>((const float4*)x);
  k_quant<<<M * K / 16 / 256, 256>>>((const float4*)x);
  {
    dim3 tg(K / 64, N / 64);    // 64 x 172
    k_transpose<<<tg, 256>>>((const int4*)W32);
  }

  cudaFuncSetAttribute(qlinear_gemm,
                       cudaFuncAttributeMaxDynamicSharedMemorySize, SMEM_TOTAL);
  qlinear_gemm<<<GEMM_CTAS, 256, SMEM_TOTAL>>>(bias, out);
}